// round 9
// baseline (speedup 1.0000x reference)
#include <cuda_runtime.h>
#include <math.h>

#define T_  256
#define B_  32
#define E_  256
#define H_  512
#define V_  2048
#define TB_ 8192
#define G4H 2048

typedef unsigned long long ull;

// ---------------- static device scratch ----------------
__device__ float g_X[TB_ * 512];                  // [t*B+b][512]
__device__ float g_G[(size_t)T_ * G4H * B_];      // [t][n][b]  (pure ih-dot, no bias)
__device__ float g_Y0[(size_t)TB_ * H_];          // [t*B+b][512]  (layer-1 ih GEMM input)
__device__ float g_Y1[(size_t)TB_ * H_];          // [t][k][b]     (logits GEMM input)
__device__ float g_logits[(size_t)TB_ * V_];
__device__ float g_hbuf[2][2][H_][B_];            // [layer][ping][k][b]
__device__ float g_rowloss[TB_];
__device__ unsigned int g_arrive[2][128 * 32];    // per-CTA arrival flags, 128B stride
__device__ unsigned int g_release[2 * 32];        // release word per layer (padded)

// ---------------- f32x2 packed helpers ----------------
__device__ __forceinline__ void ffma2(ull& d, ull a, ull b) {
    asm("fma.rn.f32x2 %0, %1, %2, %0;" : "+l"(d) : "l"(a), "l"(b));
}
__device__ __forceinline__ ull pk2(float x, float y) {
    ull r; asm("mov.b64 %0, {%1,%2};" : "=l"(r) : "f"(x), "f"(y)); return r;
}
__device__ __forceinline__ float2 upk(ull v) {
    float2 r; asm("mov.b64 {%0,%1}, %2;" : "=f"(r.x), "=f"(r.y) : "l"(v)); return r;
}

// ---------------- XLA-matched fp32 nonlinearities ----------------
__device__ __forceinline__ float xla_tanhf(float x) {
    float ax = fabsf(x);
    float xc = fminf(fmaxf(x, -9.0f), 9.0f);
    float x2 = __fmul_rn(xc, xc);
    float p = -2.76076847742355e-16f;
    p = __fadd_rn(__fmul_rn(p, x2),  2.00018790482477e-13f);
    p = __fadd_rn(__fmul_rn(p, x2), -8.60467152213735e-11f);
    p = __fadd_rn(__fmul_rn(p, x2),  5.12229709037114e-08f);
    p = __fadd_rn(__fmul_rn(p, x2),  1.48572235717979e-05f);
    p = __fadd_rn(__fmul_rn(p, x2),  6.37261928875436e-04f);
    p = __fadd_rn(__fmul_rn(p, x2),  4.89352455891786e-03f);
    float np = __fmul_rn(xc, p);
    float q = 1.19825839466702e-06f;
    q = __fadd_rn(__fmul_rn(q, x2),  1.18534705686654e-04f);
    q = __fadd_rn(__fmul_rn(q, x2),  2.26843463243900e-03f);
    q = __fadd_rn(__fmul_rn(q, x2),  4.89352518554385e-03f);
    float r = __fdiv_rn(np, q);
    return (ax < 0.0004f) ? x : r;
}
__device__ __forceinline__ float xla_sigmoidf(float x) {
    return __fdiv_rn(1.0f, __fadd_rn(1.0f, expf(-x)));
}

// ---------------- init ----------------
__global__ void init_kernel(const float* __restrict__ h0) {
    int idx = blockIdx.x * 256 + threadIdx.x;
    if (idx < 2 * 128 * 32) {
        g_arrive[idx >> 12][idx & 4095] = 0u;
        if (idx < 64) g_release[idx] = 0u;
    }
    if (idx < 2 * H_ * B_) {
        int l = idx >> 14;
        int rem = idx & 16383;
        int k = rem >> 5, b = rem & 31;
        g_hbuf[l][0][k][b] = h0[(size_t)l * B_ * H_ + (size_t)b * H_ + k];
    }
}

// ---------------- embedding gather ----------------
__global__ void embed_kernel(const int* __restrict__ pc, const int* __restrict__ delta,
                             const float* __restrict__ pc_emb, const float* __restrict__ delta_emb) {
    int r = blockIdx.x;
    int i = threadIdx.x;
    float4* dst = (float4*)(g_X + (size_t)r * 512);
    if (i < 64) dst[i] = ((const float4*)(pc_emb + (size_t)pc[r] * E_))[i];
    else        dst[i] = ((const float4*)(delta_emb + (size_t)delta[r] * E_))[i - 64];
}

// ---------------- ih GEMM: G[t][n][b] = A . W^T (no bias), FFMA2 (round-6 form) ----------------
__global__ void __launch_bounds__(256) gemm_ih_kernel(int which, const float* __restrict__ W) {
    const float* __restrict__ A = which ? g_Y0 : g_X;
    __shared__ float As[16][132];
    __shared__ float Bs[16][132];
    int tid = threadIdx.x;
    int tx = tid & 15, ty = tid >> 4;
    int bn = blockIdx.x * 128;
    int bm = blockIdx.y * 128;

    ull acc2[8][4];
#pragma unroll
    for (int i = 0; i < 8; i++)
#pragma unroll
        for (int j = 0; j < 4; j++) acc2[i][j] = 0ull;

    for (int k0 = 0; k0 < 512; k0 += 16) {
#pragma unroll
        for (int i = 0; i < 2; i++) {
            int f = tid + i * 256;
            int row = f >> 2;
            int c4 = (f & 3) * 4;
            float4 av = *(const float4*)(A + (size_t)(bm + row) * 512 + k0 + c4);
            As[c4 + 0][row] = av.x; As[c4 + 1][row] = av.y;
            As[c4 + 2][row] = av.z; As[c4 + 3][row] = av.w;
            float4 bv = *(const float4*)(W + (size_t)(bn + row) * 512 + k0 + c4);
            Bs[c4 + 0][row] = bv.x; Bs[c4 + 1][row] = bv.y;
            Bs[c4 + 2][row] = bv.z; Bs[c4 + 3][row] = bv.w;
        }
        __syncthreads();
#pragma unroll
        for (int kk = 0; kk < 16; kk++) {
            float4 a0 = *(const float4*)&As[kk][ty * 8];
            float4 a1 = *(const float4*)&As[kk][ty * 8 + 4];
            ulonglong2 b01 = *(const ulonglong2*)&Bs[kk][tx * 8];
            ulonglong2 b23 = *(const ulonglong2*)&Bs[kk][tx * 8 + 4];
            ull ap[8] = {pk2(a0.x, a0.x), pk2(a0.y, a0.y), pk2(a0.z, a0.z), pk2(a0.w, a0.w),
                         pk2(a1.x, a1.x), pk2(a1.y, a1.y), pk2(a1.z, a1.z), pk2(a1.w, a1.w)};
#pragma unroll
            for (int mi = 0; mi < 8; mi++) {
                ffma2(acc2[mi][0], ap[mi], b01.x);
                ffma2(acc2[mi][1], ap[mi], b01.y);
                ffma2(acc2[mi][2], ap[mi], b23.x);
                ffma2(acc2[mi][3], ap[mi], b23.y);
            }
        }
        __syncthreads();
    }

    float acc[8][8];
#pragma unroll
    for (int mi = 0; mi < 8; mi++)
#pragma unroll
        for (int jp = 0; jp < 4; jp++) {
            float2 f2 = upk(acc2[mi][jp]);
            acc[mi][2 * jp] = f2.x; acc[mi][2 * jp + 1] = f2.y;
        }

    int m0 = bm + ty * 8;
    int t = m0 >> 5;
    int b0 = m0 & 31;
#pragma unroll
    for (int nj = 0; nj < 8; nj++) {
        int n = bn + tx * 8 + nj;
        size_t base = ((size_t)t * G4H + n) * B_ + b0;
        float4 v0 = make_float4(acc[0][nj], acc[1][nj], acc[2][nj], acc[3][nj]);
        float4 v1 = make_float4(acc[4][nj], acc[5][nj], acc[6][nj], acc[7][nj]);
        *(float4*)(g_G + base) = v0;
        *(float4*)(g_G + base + 4) = v1;
    }
}

// ---------------- persistent LSTM layer: FFMA2 natural-layout, 128 CTAs x 256 thr ----------------
// warp q: hjl=q&3, gbase=(q<4)?0:2; lane: gsel=lane>>4 -> gate g=gbase+gsel, bp=lane&15 (b=2bp,2bp+1).
// Each thread: ONE FFMA2 chain over ascending k (bit-exact per gate/b).
__global__ void __launch_bounds__(256) lstm_kernel(const float* __restrict__ Whh,
                                                   const float* __restrict__ c0l,
                                                   int layer, int ylayout,
                                                   float* __restrict__ Y,
                                                   float* __restrict__ dout,
                                                   const float* __restrict__ bih,
                                                   const float* __restrict__ bhh) {
    extern __shared__ float sm[];
    float* h_s = sm;                               // 16384 floats [k][b] (64KB)
    ull*   w2  = (ull*)(sm + 16384);               // 16 rows x 512 ull dup-pairs (64KB)
    float2* ex2 = (float2*)(sm + 16384 + 16384);   // [gsel][hjl][bp] = 128 float2 (1KB)

    float* hbuf = &g_hbuf[layer][0][0][0];
    unsigned int* arr = &g_arrive[layer][0];
    unsigned int* rel = &g_release[layer * 32];

    int tid = threadIdx.x;
    int lane = tid & 31, q = tid >> 5;
    int hjl = q & 3;
    int gbase = (q < 4) ? 0 : 2;
    int gsel = lane >> 4;
    int bp = lane & 15;
    int g = gbase + gsel;
    int hj = blockIdx.x * 4 + hjl;
    int wrow = hjl * 4 + g;
    int n = g * 512 + hj;
    float bias = __fadd_rn(bih[n], bhh[n]);

    // pack W_hh dup-pairs once: row = hjl*4 + gate
    for (int e = tid; e < 8192; e += 256) {
        int row = e >> 9;
        int k = e & 511;
        int gg = row & 3, hl = row >> 2;
        float w = Whh[((size_t)gg * 512 + blockIdx.x * 4 + hl) * 512 + k];
        w2[row * 512 + k] = pk2(w, w);
    }

    // c state lives in i-lanes (warps 0-3, lanes 0-15)
    float c0r = 0.0f, c1r = 0.0f;
    if (q < 4 && lane < 16) {
        c0r = c0l[(size_t)(2 * bp) * 512 + hj];
        c1r = c0l[(size_t)(2 * bp + 1) * 512 + hj];
    }
    __syncthreads();

    const ull* wk = w2 + wrow * 512;
    int ping = 0;
    for (int t = 0; t < 256; t++) {
        // stage h (round-6 verbatim: plain float4 copy, no repacking)
        const float* hsrc = hbuf + ping * 16384;
        for (int i = tid * 4; i < 16384; i += 1024)
            *(float4*)(h_s + i) = *(const float4*)(hsrc + i);
        __syncthreads();

        // prefetch G for this (gate, b-pair)
        float2 Gv = *(const float2*)(g_G + ((size_t)t * G4H + n) * B_ + 2 * bp);

        // dot: single FFMA2 chain, ascending k; h pairs are natural b64 in [k][b]
        ull acc = 0ull;
#pragma unroll 8
        for (int k = 0; k < 512; k += 2) {
            ulonglong2 wv = *(const ulonglong2*)(wk + k);
            ull h0 = *(const ull*)(h_s + (k + 0) * 32 + 2 * bp);
            ull h1 = *(const ull*)(h_s + (k + 1) * 32 + 2 * bp);
            ffma2(acc, h0, wv.x);
            ffma2(acc, h1, wv.y);
        }
        float2 d = upk(acc);
        float p0 = __fadd_rn(__fadd_rn(Gv.x, d.x), bias);
        float p1 = __fadd_rn(__fadd_rn(Gv.y, d.y), bias);

        // second gate of this warp's pair -> lower lanes via shfl
        float f0 = __shfl_sync(0xffffffffu, p0, lane | 16);
        float f1 = __shfl_sync(0xffffffffu, p1, lane | 16);

        // g,o warps publish pre-acts
        if (q >= 4) ex2[(gsel * 4 + hjl) * 16 + bp] = make_float2(p0, p1);
        __syncthreads();

        if (q < 4 && lane < 16) {
            float2 gg = ex2[(0 * 4 + hjl) * 16 + bp];
            float2 oo = ex2[(1 * 4 + hjl) * 16 + bp];
            float ig0 = xla_sigmoidf(p0);
            float fg0 = xla_sigmoidf(f0);
            float tg0 = xla_tanhf(gg.x);
            float og0 = xla_sigmoidf(oo.x);
            c0r = __fadd_rn(__fmul_rn(fg0, c0r), __fmul_rn(ig0, tg0));
            float h0 = __fmul_rn(og0, xla_tanhf(c0r));
            float ig1 = xla_sigmoidf(p1);
            float fg1 = xla_sigmoidf(f1);
            float tg1 = xla_tanhf(gg.y);
            float og1 = xla_sigmoidf(oo.y);
            c1r = __fadd_rn(__fmul_rn(fg1, c1r), __fmul_rn(ig1, tg1));
            float h1 = __fmul_rn(og1, xla_tanhf(c1r));

            *(float2*)(hbuf + (ping ^ 1) * 16384 + hj * 32 + 2 * bp) = make_float2(h0, h1);
            if (ylayout) {
                *(float2*)(Y + (size_t)t * 16384 + hj * 32 + 2 * bp) = make_float2(h0, h1);
            } else {
                Y[((size_t)t * 32 + 2 * bp) * 512 + hj]     = h0;
                Y[((size_t)t * 32 + 2 * bp + 1) * 512 + hj] = h1;
            }
            if (t == 255) {
                int b0i = 2 * bp, b1i = 2 * bp + 1;
                dout[81921  + (size_t)layer * 16384 + (size_t)b0i * 512 + hj] = h0;
                dout[81921  + (size_t)layer * 16384 + (size_t)b1i * 512 + hj] = h1;
                dout[114689 + (size_t)layer * 16384 + (size_t)b0i * 512 + hj] = c0r;
                dout[114689 + (size_t)layer * 16384 + (size_t)b1i * 512 + hj] = c1r;
            }
        }

        // distributed grid barrier: per-CTA flags + CTA0 aggregation + release broadcast
        __syncthreads();
        unsigned int tag = (unsigned)(t + 1);
        if (tid == 0) {
            __threadfence();
            *(volatile unsigned int*)&arr[blockIdx.x * 32] = tag;
        }
        if (blockIdx.x == 0) {
            if (tid < 128) {
                while (*(volatile unsigned int*)&arr[tid * 32] < tag) { }
            }
            __syncthreads();
            if (tid == 0) {
                __threadfence();
                *(volatile unsigned int*)rel = tag;
            }
        }
        if (tid == 0) {
            while (*(volatile unsigned int*)rel < tag) { }
            __threadfence();
        }
        __syncthreads();
        ping ^= 1;
    }
}

// ---------------- cluster-routed projection, FFMA2 (round-6 form). Y1 layout [t][k][b] ----------------
__global__ void __launch_bounds__(256) logits_kernel(const int* __restrict__ clusters,
                                                     const float* __restrict__ Wc,
                                                     const float* __restrict__ bc) {
    __shared__ float As[32][36];
    __shared__ float Bs[32][132];
    int tid = threadIdx.x;
    int t = blockIdx.y;
    int c = clusters[t];
    int n0 = blockIdx.x * 128;
    int tm = tid >> 5, tn = tid & 31;

    ull acc2[4][2];
#pragma unroll
    for (int i = 0; i < 4; i++) { acc2[i][0] = 0ull; acc2[i][1] = 0ull; }

    for (int k0 = 0; k0 < 512; k0 += 32) {
        {
            int kk = tid >> 3, mq = tid & 7;
            *(float4*)&As[kk][mq * 4] =
                *(const float4*)(g_Y1 + (size_t)t * 16384 + (size_t)(k0 + kk) * 32 + mq * 4);
        }
#pragma unroll
        for (int i = 0; i < 4; i++) {
            int idx = tid + i * 256;
            int kk = idx >> 5, c4 = (idx & 31) * 4;
            float4 bv = *(const float4*)(Wc + ((size_t)c * 512 + k0 + kk) * 2048 + n0 + c4);
            *(float4*)&Bs[kk][c4] = bv;
        }
        __syncthreads();
#pragma unroll
        for (int kk = 0; kk < 32; kk++) {
            float4 a = *(const float4*)&As[kk][tm * 4];
            ulonglong2 bp = *(const ulonglong2*)&Bs[kk][tn * 4];
            ull ap0 = pk2(a.x, a.x), ap1 = pk2(a.y, a.y), ap2 = pk2(a.z, a.z), ap3 = pk2(a.w, a.w);
            ffma2(acc2[0][0], ap0, bp.x); ffma2(acc2[0][1], ap0, bp.y);
            ffma2(acc2[1][0], ap1, bp.x); ffma2(acc2[1][1], ap1, bp.y);
            ffma2(acc2[2][0], ap2, bp.x); ffma2(acc2[2][1], ap2, bp.y);
            ffma2(acc2[3][0], ap3, bp.x); ffma2(acc2[3][1], ap3, bp.y);
        }
        __syncthreads();
    }
#pragma unroll
    for (int mi = 0; mi < 4; mi++) {
        float2 x0 = upk(acc2[mi][0]), x1 = upk(acc2[mi][1]);
        int row = t * 32 + tm * 4 + mi;
        int col = n0 + tn * 4;
        float4 bv = *(const float4*)(bc + (size_t)c * 2048 + col);
        float4 v = make_float4(__fadd_rn(x0.x, bv.x), __fadd_rn(x0.y, bv.y),
                               __fadd_rn(x1.x, bv.z), __fadd_rn(x1.y, bv.w));
        *(float4*)(g_logits + (size_t)row * 2048 + col) = v;
    }
}

// ---------------- log-softmax + loss + top-10 per row ----------------
__global__ void __launch_bounds__(256) softmax_topk_kernel(const int* __restrict__ target,
                                                           float* __restrict__ dout) {
    int r = blockIdx.x;
    int tid = threadIdx.x;
    const float* L = g_logits + (size_t)r * 2048;
    float v[8];
#pragma unroll
    for (int j = 0; j < 8; j++) v[j] = L[tid + j * 256];

    __shared__ float  sv[8];
    __shared__ int    si[8];
    __shared__ double sd[8];
    __shared__ float  sbc;

    float m = -INFINITY;
#pragma unroll
    for (int j = 0; j < 8; j++) m = fmaxf(m, v[j]);
#pragma unroll
    for (int o = 16; o > 0; o >>= 1) m = fmaxf(m, __shfl_xor_sync(0xffffffffu, m, o));
    if ((tid & 31) == 0) sv[tid >> 5] = m;
    __syncthreads();
    if (tid == 0) {
        float mm = sv[0];
        for (int w = 1; w < 8; w++) mm = fmaxf(mm, sv[w]);
        sv[0] = mm;
    }
    __syncthreads();
    float M = sv[0];

    float sf[8];
    double s = 0.0;
#pragma unroll
    for (int j = 0; j < 8; j++) {
        sf[j] = __fadd_rn(v[j], -M);
        s += (double)expf(sf[j]);
    }
#pragma unroll
    for (int o = 16; o > 0; o >>= 1) s += __shfl_xor_sync(0xffffffffu, s, o);
    if ((tid & 31) == 0) sd[tid >> 5] = s;
    __syncthreads();
    if (tid == 0) {
        double ss = 0.0;
        for (int w = 0; w < 8; w++) ss += sd[w];
        double logS = log(ss);
        sbc = (float)logS;
        float sft = __fadd_rn(L[target[r]], -M);
        g_rowloss[r] = (float)(logS - (double)sft);
    }
    __syncthreads();
    float logS_f = sbc;

    float qv[8];
#pragma unroll
    for (int j = 0; j < 8; j++) qv[j] = __fadd_rn(sf[j], -logS_f);

    for (int it = 0; it < 10; it++) {
        float bv = -INFINITY;
        int bi = 1 << 30;
#pragma unroll
        for (int j = 0; j < 8; j++) {
            int gi = tid + j * 256;
            if (qv[j] > bv || (qv[j] == bv && gi < bi)) { bv = qv[j]; bi = gi; }
        }
#pragma unroll
        for (int o = 16; o > 0; o >>= 1) {
            float ov = __shfl_xor_sync(0xffffffffu, bv, o);
            int   oi = __shfl_xor_sync(0xffffffffu, bi, o);
            if (ov > bv || (ov == bv && oi < bi)) { bv = ov; bi = oi; }
        }
        if ((tid & 31) == 0) { sv[tid >> 5] = bv; si[tid >> 5] = bi; }
        __syncthreads();
        if (tid == 0) {
            float wv = sv[0]; int wi = si[0];
            for (int w = 1; w < 8; w++)
                if (sv[w] > wv || (sv[w] == wv && si[w] < wi)) { wv = sv[w]; wi = si[w]; }
            si[0] = wi;
            dout[1 + (size_t)r * 10 + it] = (float)wi;
        }
        __syncthreads();
        int wi = si[0];
        if ((wi & 255) == tid) qv[wi >> 8] = -INFINITY;
        __syncthreads();
    }
}

// ---------------- deterministic loss reduction (double) ----------------
__global__ void __launch_bounds__(256) loss_kernel(float* __restrict__ dout) {
    __shared__ double s[256];
    int tid = threadIdx.x;
    double a = 0.0;
    for (int i = 0; i < 32; i++) a += (double)g_rowloss[tid * 32 + i];
    s[tid] = a;
    __syncthreads();
    for (int o = 128; o > 0; o >>= 1) {
        if (tid < o) s[tid] += s[tid + o];
        __syncthreads();
    }
    if (tid == 0) dout[0] = (float)(s[0] / 8192.0);
}

extern "C" void kernel_launch(void* const* d_in, const int* in_sizes, int n_in,
                              void* d_out, int out_size) {
    const int*   pc        = (const int*)d_in[0];
    const int*   delta     = (const int*)d_in[1];
    const int*   clusters  = (const int*)d_in[2];
    const int*   target    = (const int*)d_in[3];
    const float* h0        = (const float*)d_in[4];
    const float* c0        = (const float*)d_in[5];
    const float* pc_emb    = (const float*)d_in[6];
    const float* delta_emb = (const float*)d_in[7];
    const float* w_ih0     = (const float*)d_in[8];
    const float* w_hh0     = (const float*)d_in[9];
    const float* b_ih0     = (const float*)d_in[10];
    const float* b_hh0     = (const float*)d_in[11];
    const float* w_ih1     = (const float*)d_in[12];
    const float* w_hh1     = (const float*)d_in[13];
    const float* b_ih1     = (const float*)d_in[14];
    const float* b_hh1     = (const float*)d_in[15];
    const float* Wc        = (const float*)d_in[16];
    const float* bc        = (const float*)d_in[17];
    float* out = (float*)d_out;

    static int smem_set = 0;
    int lstm_smem = 65536 + 65536 + 1024;
    if (!smem_set) {
        cudaFuncSetAttribute(lstm_kernel, cudaFuncAttributeMaxDynamicSharedMemorySize, lstm_smem);
        smem_set = 1;
    }

    float* g_Y0p = nullptr; float* g_Y1p = nullptr;
    cudaGetSymbolAddress((void**)&g_Y0p, g_Y0);
    cudaGetSymbolAddress((void**)&g_Y1p, g_Y1);

    init_kernel<<<128, 256>>>(h0);
    embed_kernel<<<TB_, 128>>>(pc, delta, pc_emb, delta_emb);
    gemm_ih_kernel<<<dim3(16, 64), 256>>>(0, w_ih0);
    lstm_kernel<<<128, 256, lstm_smem>>>(w_hh0, c0, 0, 0, g_Y0p, out, b_ih0, b_hh0);
    gemm_ih_kernel<<<dim3(16, 64), 256>>>(1, w_ih1);
    lstm_kernel<<<128, 256, lstm_smem>>>(w_hh1, c0 + (size_t)B_ * H_, 1, 1, g_Y1p, out, b_ih1, b_hh1);
    logits_kernel<<<dim3(16, 256), 256>>>(clusters, Wc, bc);
    softmax_topk_kernel<<<TB_, 256>>>(target, out);
    loss_kernel<<<1, 256>>>(out);
}

// round 10
// speedup vs baseline: 1.2273x; 1.2273x over previous
#include <cuda_runtime.h>
#include <math.h>

#define T_  256
#define B_  32
#define E_  256
#define H_  512
#define V_  2048
#define TB_ 8192
#define G4H 2048

typedef unsigned long long ull;

// ---------------- static device scratch ----------------
__device__ float g_X[TB_ * 512];                  // [t*B+b][512]
__device__ float g_G[(size_t)T_ * G4H * B_];      // [t][n][b]  (pure ih-dot, no bias)
__device__ float g_Y0[(size_t)TB_ * H_];          // [t*B+b][512]  (layer-1 ih GEMM input)
__device__ float g_Y1[(size_t)TB_ * H_];          // [t][k][b]     (logits GEMM input)
__device__ float g_logits[(size_t)TB_ * V_];
__device__ float g_hbuf[2][2][H_][B_];            // [layer][ping][k][b]
__device__ float g_rowloss[TB_];
__device__ unsigned int g_bar[2];

// ---------------- f32x2 packed helpers ----------------
__device__ __forceinline__ void ffma2(ull& d, ull a, ull b) {
    asm("fma.rn.f32x2 %0, %1, %2, %0;" : "+l"(d) : "l"(a), "l"(b));
}
__device__ __forceinline__ ull pk2(float x, float y) {
    ull r; asm("mov.b64 %0, {%1,%2};" : "=l"(r) : "f"(x), "f"(y)); return r;
}
__device__ __forceinline__ float2 upk(ull v) {
    float2 r; asm("mov.b64 {%0,%1}, %2;" : "=f"(r.x), "=f"(r.y) : "l"(v)); return r;
}

// ---------------- XLA-matched fp32 nonlinearities ----------------
__device__ __forceinline__ float xla_tanhf(float x) {
    float ax = fabsf(x);
    float xc = fminf(fmaxf(x, -9.0f), 9.0f);
    float x2 = __fmul_rn(xc, xc);
    float p = -2.76076847742355e-16f;
    p = __fadd_rn(__fmul_rn(p, x2),  2.00018790482477e-13f);
    p = __fadd_rn(__fmul_rn(p, x2), -8.60467152213735e-11f);
    p = __fadd_rn(__fmul_rn(p, x2),  5.12229709037114e-08f);
    p = __fadd_rn(__fmul_rn(p, x2),  1.48572235717979e-05f);
    p = __fadd_rn(__fmul_rn(p, x2),  6.37261928875436e-04f);
    p = __fadd_rn(__fmul_rn(p, x2),  4.89352455891786e-03f);
    float np = __fmul_rn(xc, p);
    float q = 1.19825839466702e-06f;
    q = __fadd_rn(__fmul_rn(q, x2),  1.18534705686654e-04f);
    q = __fadd_rn(__fmul_rn(q, x2),  2.26843463243900e-03f);
    q = __fadd_rn(__fmul_rn(q, x2),  4.89352518554385e-03f);
    float r = __fdiv_rn(np, q);
    return (ax < 0.0004f) ? x : r;
}
__device__ __forceinline__ float xla_sigmoidf(float x) {
    return __fdiv_rn(1.0f, __fadd_rn(1.0f, expf(-x)));
}

// ---------------- init ----------------
__global__ void init_kernel(const float* __restrict__ h0) {
    int idx = blockIdx.x * 256 + threadIdx.x;
    if (idx < 2) g_bar[idx] = 0u;
    if (idx < 2 * H_ * B_) {
        int l = idx >> 14;
        int rem = idx & 16383;
        int k = rem >> 5, b = rem & 31;
        g_hbuf[l][0][k][b] = h0[(size_t)l * B_ * H_ + (size_t)b * H_ + k];
    }
}

// ---------------- embedding gather ----------------
__global__ void embed_kernel(const int* __restrict__ pc, const int* __restrict__ delta,
                             const float* __restrict__ pc_emb, const float* __restrict__ delta_emb) {
    int r = blockIdx.x;
    int i = threadIdx.x;
    float4* dst = (float4*)(g_X + (size_t)r * 512);
    if (i < 64) dst[i] = ((const float4*)(pc_emb + (size_t)pc[r] * E_))[i];
    else        dst[i] = ((const float4*)(delta_emb + (size_t)delta[r] * E_))[i - 64];
}

// ---------------- ih GEMM: G[t][n][b] = A . W^T, FFMA2, register-prefetch pipelined ----------------
__global__ void __launch_bounds__(256) gemm_ih_kernel(int which, const float* __restrict__ W) {
    const float* __restrict__ A = which ? g_Y0 : g_X;
    __shared__ float As[16][132];
    __shared__ float Bs[16][132];
    int tid = threadIdx.x;
    int tx = tid & 15, ty = tid >> 4;
    int bn = blockIdx.x * 128;
    int bm = blockIdx.y * 128;

    // per-thread staging coordinates (two 16B fragments per array)
    int row0 = tid >> 2,          c40 = (tid & 3) * 4;
    int row1 = (tid + 256) >> 2,  c41 = ((tid + 256) & 3) * 4;
    const float* a0p = A + (size_t)(bm + row0) * 512 + c40;
    const float* a1p = A + (size_t)(bm + row1) * 512 + c41;
    const float* b0p = W + (size_t)(bn + row0) * 512 + c40;
    const float* b1p = W + (size_t)(bn + row1) * 512 + c41;

    ull acc2[8][4];
#pragma unroll
    for (int i = 0; i < 8; i++)
#pragma unroll
        for (int j = 0; j < 4; j++) acc2[i][j] = 0ull;

    // prologue prefetch of tile 0
    float4 pa0 = *(const float4*)(a0p);
    float4 pa1 = *(const float4*)(a1p);
    float4 pb0 = *(const float4*)(b0p);
    float4 pb1 = *(const float4*)(b1p);

    for (int it = 0; it < 32; it++) {
        // store prefetched tile to smem
        As[c40 + 0][row0] = pa0.x; As[c40 + 1][row0] = pa0.y;
        As[c40 + 2][row0] = pa0.z; As[c40 + 3][row0] = pa0.w;
        As[c41 + 0][row1] = pa1.x; As[c41 + 1][row1] = pa1.y;
        As[c41 + 2][row1] = pa1.z; As[c41 + 3][row1] = pa1.w;
        Bs[c40 + 0][row0] = pb0.x; Bs[c40 + 1][row0] = pb0.y;
        Bs[c40 + 2][row0] = pb0.z; Bs[c40 + 3][row0] = pb0.w;
        Bs[c41 + 0][row1] = pb1.x; Bs[c41 + 1][row1] = pb1.y;
        Bs[c41 + 2][row1] = pb1.z; Bs[c41 + 3][row1] = pb1.w;
        // issue LDGs for next tile (hidden under this tile's compute)
        if (it < 31) {
            int k0 = (it + 1) * 16;
            pa0 = *(const float4*)(a0p + k0);
            pa1 = *(const float4*)(a1p + k0);
            pb0 = *(const float4*)(b0p + k0);
            pb1 = *(const float4*)(b1p + k0);
        }
        __syncthreads();
#pragma unroll
        for (int kk = 0; kk < 16; kk++) {
            float4 a0 = *(const float4*)&As[kk][ty * 8];
            float4 a1 = *(const float4*)&As[kk][ty * 8 + 4];
            ulonglong2 b01 = *(const ulonglong2*)&Bs[kk][tx * 8];
            ulonglong2 b23 = *(const ulonglong2*)&Bs[kk][tx * 8 + 4];
            ull ap[8] = {pk2(a0.x, a0.x), pk2(a0.y, a0.y), pk2(a0.z, a0.z), pk2(a0.w, a0.w),
                         pk2(a1.x, a1.x), pk2(a1.y, a1.y), pk2(a1.z, a1.z), pk2(a1.w, a1.w)};
#pragma unroll
            for (int mi = 0; mi < 8; mi++) {
                ffma2(acc2[mi][0], ap[mi], b01.x);
                ffma2(acc2[mi][1], ap[mi], b01.y);
                ffma2(acc2[mi][2], ap[mi], b23.x);
                ffma2(acc2[mi][3], ap[mi], b23.y);
            }
        }
        __syncthreads();
    }

    float acc[8][8];
#pragma unroll
    for (int mi = 0; mi < 8; mi++)
#pragma unroll
        for (int jp = 0; jp < 4; jp++) {
            float2 f2 = upk(acc2[mi][jp]);
            acc[mi][2 * jp] = f2.x; acc[mi][2 * jp + 1] = f2.y;
        }

    int m0 = bm + ty * 8;
    int t = m0 >> 5;
    int b0 = m0 & 31;
#pragma unroll
    for (int nj = 0; nj < 8; nj++) {
        int n = bn + tx * 8 + nj;
        size_t base = ((size_t)t * G4H + n) * B_ + b0;
        float4 v0 = make_float4(acc[0][nj], acc[1][nj], acc[2][nj], acc[3][nj]);
        float4 v1 = make_float4(acc[4][nj], acc[5][nj], acc[6][nj], acc[7][nj]);
        *(float4*)(g_G + base) = v0;
        *(float4*)(g_G + base + 4) = v1;
    }
}

// ---------------- persistent LSTM layer (round-6 scalar form, 128 CTAs x 256 thr) ----------------
__global__ void __launch_bounds__(256) lstm_kernel(const float* __restrict__ Whh,
                                                   const float* __restrict__ c0l,
                                                   int layer, int ylayout,
                                                   float* __restrict__ Y,
                                                   float* __restrict__ dout,
                                                   const float* __restrict__ bih,
                                                   const float* __restrict__ bhh) {
    extern __shared__ float sm[];
    float* h_s = sm;                 // 16384 floats [k][b]
    float* w_s = sm + 16384;         // 8192 : 16 rows (hl*4+g) x 512
    float* ex  = sm + 24576;         // 256  : [hjl*32+b]*2
    float* c_s = sm + 24832;         // 128

    float* hbuf = &g_hbuf[layer][0][0][0];
    unsigned int* bar = &g_bar[layer];

    int tid = threadIdx.x;
    int b = tid & 31, q = tid >> 5;
    int hjl = q & 3;
    int hj = blockIdx.x * 4 + hjl;
    int gbase = (q < 4) ? 0 : 2;     // gates (i,f) or (g,o)

    for (int i = tid; i < 2048; i += 256) {      // 2048 float4 of W_hh slice
        int r = i >> 7;
        int c4 = (i & 127) * 4;
        int g = r & 3, hl = r >> 2;
        *(float4*)(w_s + r * 512 + c4) =
            *(const float4*)(Whh + ((size_t)g * 512 + blockIdx.x * 4 + hl) * 512 + c4);
    }
    if (tid < 128) {
        int hl = tid >> 5, bb = tid & 31;
        c_s[hl * 32 + bb] = c0l[(size_t)bb * 512 + blockIdx.x * 4 + hl];
    }
    const float* w0 = w_s + (hjl * 4 + gbase) * 512;
    const float* w1 = w0 + 512;
    int n0g = gbase * 512 + hj;
    int n1g = (gbase + 1) * 512 + hj;
    float bias0 = __fadd_rn(bih[n0g], bhh[n0g]);
    float bias1 = __fadd_rn(bih[n1g], bhh[n1g]);
    __syncthreads();

    int ping = 0;
    for (int t = 0; t < 256; t++) {
        const float* hsrc = hbuf + ping * 16384;
        for (int i = tid * 4; i < 16384; i += 1024)
            *(float4*)(h_s + i) = *(const float4*)(hsrc + i);
        __syncthreads();

        float acc0 = 0.0f, acc1 = 0.0f;
#pragma unroll 4
        for (int k = 0; k < 512; k += 4) {
            float4 wa = *(const float4*)(w0 + k);
            float4 wb = *(const float4*)(w1 + k);
            float h0v = h_s[(k + 0) * 32 + b];
            float h1v = h_s[(k + 1) * 32 + b];
            float h2v = h_s[(k + 2) * 32 + b];
            float h3v = h_s[(k + 3) * 32 + b];
            acc0 = fmaf(h0v, wa.x, acc0); acc1 = fmaf(h0v, wb.x, acc1);
            acc0 = fmaf(h1v, wa.y, acc0); acc1 = fmaf(h1v, wb.y, acc1);
            acc0 = fmaf(h2v, wa.z, acc0); acc1 = fmaf(h2v, wb.z, acc1);
            acc0 = fmaf(h3v, wa.w, acc0); acc1 = fmaf(h3v, wb.w, acc1);
        }

        float G0 = g_G[((size_t)t * G4H + n0g) * B_ + b];
        float G1 = g_G[((size_t)t * G4H + n1g) * B_ + b];
        float pre0 = __fadd_rn(__fadd_rn(G0, acc0), bias0);
        float pre1 = __fadd_rn(__fadd_rn(G1, acc1), bias1);

        if (q >= 4) {                 // g, o pre-activations
            ex[(hjl * 32 + b) * 2 + 0] = pre0;
            ex[(hjl * 32 + b) * 2 + 1] = pre1;
        }
        __syncthreads();
        if (q < 4) {                  // i=pre0, f=pre1
            float pre_g = ex[(hjl * 32 + b) * 2 + 0];
            float pre_o = ex[(hjl * 32 + b) * 2 + 1];
            float ig = xla_sigmoidf(pre0);
            float fg = xla_sigmoidf(pre1);
            float tg = xla_tanhf(pre_g);
            float og = xla_sigmoidf(pre_o);
            float cold = c_s[hjl * 32 + b];
            float cn = __fadd_rn(__fmul_rn(fg, cold), __fmul_rn(ig, tg));
            float hn = __fmul_rn(og, xla_tanhf(cn));
            c_s[hjl * 32 + b] = cn;
            hbuf[(ping ^ 1) * 16384 + hj * 32 + b] = hn;
            if (ylayout) Y[(size_t)t * 16384 + hj * 32 + b] = hn;
            else         Y[((size_t)t * 32 + b) * 512 + hj] = hn;
            if (t == 255) {
                dout[81921  + (size_t)layer * 16384 + (size_t)b * 512 + hj] = hn;
                dout[114689 + (size_t)layer * 16384 + (size_t)b * 512 + hj] = cn;
            }
        }
        __syncthreads();
        if (tid == 0) {
            __threadfence();
            atomicAdd(bar, 1u);
            unsigned int target = 128u * (unsigned)(t + 1);
            volatile unsigned int* vb = (volatile unsigned int*)bar;
            while (*vb < target) { }
            __threadfence();
        }
        __syncthreads();
        ping ^= 1;
    }
}

// ---------------- cluster-routed projection, FFMA2, register-prefetch pipelined ----------------
__global__ void __launch_bounds__(256) logits_kernel(const int* __restrict__ clusters,
                                                     const float* __restrict__ Wc,
                                                     const float* __restrict__ bc) {
    __shared__ float As[32][36];
    __shared__ float Bs[32][132];
    int tid = threadIdx.x;
    int t = blockIdx.y;
    int c = clusters[t];
    int n0 = blockIdx.x * 128;
    int tm = tid >> 5, tn = tid & 31;

    // staging coordinates
    int kk_a = tid >> 3, mq = tid & 7;
    const float* ap = g_Y1 + (size_t)t * 16384 + (size_t)kk_a * 32 + mq * 4;   // +k0*32 per tile
    int kk_b[4], c4_b[4];
    const float* bp4[4];
#pragma unroll
    for (int i = 0; i < 4; i++) {
        int idx = tid + i * 256;
        kk_b[i] = idx >> 5; c4_b[i] = (idx & 31) * 4;
        bp4[i] = Wc + ((size_t)c * 512 + kk_b[i]) * 2048 + n0 + c4_b[i];       // +k0*2048 per tile
    }

    ull acc2[4][2];
#pragma unroll
    for (int i = 0; i < 4; i++) { acc2[i][0] = 0ull; acc2[i][1] = 0ull; }

    // prologue prefetch tile 0
    float4 pa = *(const float4*)(ap);
    float4 pb[4];
#pragma unroll
    for (int i = 0; i < 4; i++) pb[i] = *(const float4*)(bp4[i]);

    for (int it = 0; it < 16; it++) {
        // store prefetched tile
        *(float4*)&As[kk_a][mq * 4] = pa;
#pragma unroll
        for (int i = 0; i < 4; i++) *(float4*)&Bs[kk_b[i]][c4_b[i]] = pb[i];
        // prefetch next tile
        if (it < 15) {
            int k0 = (it + 1) * 32;
            pa = *(const float4*)(ap + (size_t)k0 * 32);
#pragma unroll
            for (int i = 0; i < 4; i++) pb[i] = *(const float4*)(bp4[i] + (size_t)k0 * 2048);
        }
        __syncthreads();
#pragma unroll
        for (int kk = 0; kk < 32; kk++) {
            float4 a = *(const float4*)&As[kk][tm * 4];
            ulonglong2 bq = *(const ulonglong2*)&Bs[kk][tn * 4];
            ull ap0 = pk2(a.x, a.x), ap1 = pk2(a.y, a.y), ap2 = pk2(a.z, a.z), ap3 = pk2(a.w, a.w);
            ffma2(acc2[0][0], ap0, bq.x); ffma2(acc2[0][1], ap0, bq.y);
            ffma2(acc2[1][0], ap1, bq.x); ffma2(acc2[1][1], ap1, bq.y);
            ffma2(acc2[2][0], ap2, bq.x); ffma2(acc2[2][1], ap2, bq.y);
            ffma2(acc2[3][0], ap3, bq.x); ffma2(acc2[3][1], ap3, bq.y);
        }
        __syncthreads();
    }
#pragma unroll
    for (int mi = 0; mi < 4; mi++) {
        float2 x0 = upk(acc2[mi][0]), x1 = upk(acc2[mi][1]);
        int row = t * 32 + tm * 4 + mi;
        int col = n0 + tn * 4;
        float4 bv = *(const float4*)(bc + (size_t)c * 2048 + col);
        float4 v = make_float4(__fadd_rn(x0.x, bv.x), __fadd_rn(x0.y, bv.y),
                               __fadd_rn(x1.x, bv.z), __fadd_rn(x1.y, bv.w));
        *(float4*)(g_logits + (size_t)row * 2048 + col) = v;
    }
}

// ---------------- log-softmax + loss + top-10 per row ----------------
__global__ void __launch_bounds__(256) softmax_topk_kernel(const int* __restrict__ target,
                                                           float* __restrict__ dout) {
    int r = blockIdx.x;
    int tid = threadIdx.x;
    const float* L = g_logits + (size_t)r * 2048;
    float v[8];
#pragma unroll
    for (int j = 0; j < 8; j++) v[j] = L[tid + j * 256];

    __shared__ float  sv[8];
    __shared__ int    si[8];
    __shared__ double sd[8];
    __shared__ float  sbc;

    float m = -INFINITY;
#pragma unroll
    for (int j = 0; j < 8; j++) m = fmaxf(m, v[j]);
#pragma unroll
    for (int o = 16; o > 0; o >>= 1) m = fmaxf(m, __shfl_xor_sync(0xffffffffu, m, o));
    if ((tid & 31) == 0) sv[tid >> 5] = m;
    __syncthreads();
    if (tid == 0) {
        float mm = sv[0];
        for (int w = 1; w < 8; w++) mm = fmaxf(mm, sv[w]);
        sv[0] = mm;
    }
    __syncthreads();
    float M = sv[0];

    float sf[8];
    double s = 0.0;
#pragma unroll
    for (int j = 0; j < 8; j++) {
        sf[j] = __fadd_rn(v[j], -M);
        s += (double)expf(sf[j]);
    }
#pragma unroll
    for (int o = 16; o > 0; o >>= 1) s += __shfl_xor_sync(0xffffffffu, s, o);
    if ((tid & 31) == 0) sd[tid >> 5] = s;
    __syncthreads();
    if (tid == 0) {
        double ss = 0.0;
        for (int w = 0; w < 8; w++) ss += sd[w];
        double logS = log(ss);
        sbc = (float)logS;
        float sft = __fadd_rn(L[target[r]], -M);
        g_rowloss[r] = (float)(logS - (double)sft);
    }
    __syncthreads();
    float logS_f = sbc;

    float qv[8];
#pragma unroll
    for (int j = 0; j < 8; j++) qv[j] = __fadd_rn(sf[j], -logS_f);

    for (int it = 0; it < 10; it++) {
        float bv = -INFINITY;
        int bi = 1 << 30;
#pragma unroll
        for (int j = 0; j < 8; j++) {
            int gi = tid + j * 256;
            if (qv[j] > bv || (qv[j] == bv && gi < bi)) { bv = qv[j]; bi = gi; }
        }
#pragma unroll
        for (int o = 16; o > 0; o >>= 1) {
            float ov = __shfl_xor_sync(0xffffffffu, bv, o);
            int   oi = __shfl_xor_sync(0xffffffffu, bi, o);
            if (ov > bv || (ov == bv && oi < bi)) { bv = ov; bi = oi; }
        }
        if ((tid & 31) == 0) { sv[tid >> 5] = bv; si[tid >> 5] = bi; }
        __syncthreads();
        if (tid == 0) {
            float wv = sv[0]; int wi = si[0];
            for (int w = 1; w < 8; w++)
                if (sv[w] > wv || (sv[w] == wv && si[w] < wi)) { wv = sv[w]; wi = si[w]; }
            si[0] = wi;
            dout[1 + (size_t)r * 10 + it] = (float)wi;
        }
        __syncthreads();
        int wi = si[0];
        if ((wi & 255) == tid) qv[wi >> 8] = -INFINITY;
        __syncthreads();
    }
}

// ---------------- deterministic loss reduction (double) ----------------
__global__ void __launch_bounds__(256) loss_kernel(float* __restrict__ dout) {
    __shared__ double s[256];
    int tid = threadIdx.x;
    double a = 0.0;
    for (int i = 0; i < 32; i++) a += (double)g_rowloss[tid * 32 + i];
    s[tid] = a;
    __syncthreads();
    for (int o = 128; o > 0; o >>= 1) {
        if (tid < o) s[tid] += s[tid + o];
        __syncthreads();
    }
    if (tid == 0) dout[0] = (float)(s[0] / 8192.0);
}

extern "C" void kernel_launch(void* const* d_in, const int* in_sizes, int n_in,
                              void* d_out, int out_size) {
    const int*   pc        = (const int*)d_in[0];
    const int*   delta     = (const int*)d_in[1];
    const int*   clusters  = (const int*)d_in[2];
    const int*   target    = (const int*)d_in[3];
    const float* h0        = (const float*)d_in[4];
    const float* c0        = (const float*)d_in[5];
    const float* pc_emb    = (const float*)d_in[6];
    const float* delta_emb = (const float*)d_in[7];
    const float* w_ih0     = (const float*)d_in[8];
    const float* w_hh0     = (const float*)d_in[9];
    const float* b_ih0     = (const float*)d_in[10];
    const float* b_hh0     = (const float*)d_in[11];
    const float* w_ih1     = (const float*)d_in[12];
    const float* w_hh1     = (const float*)d_in[13];
    const float* b_ih1     = (const float*)d_in[14];
    const float* b_hh1     = (const float*)d_in[15];
    const float* Wc        = (const float*)d_in[16];
    const float* bc        = (const float*)d_in[17];
    float* out = (float*)d_out;

    static int smem_set = 0;
    int lstm_smem = 24960 * 4;
    if (!smem_set) {
        cudaFuncSetAttribute(lstm_kernel, cudaFuncAttributeMaxDynamicSharedMemorySize, lstm_smem);
        smem_set = 1;
    }

    float* g_Y0p = nullptr; float* g_Y1p = nullptr;
    cudaGetSymbolAddress((void**)&g_Y0p, g_Y0);
    cudaGetSymbolAddress((void**)&g_Y1p, g_Y1);

    init_kernel<<<128, 256>>>(h0);
    embed_kernel<<<TB_, 128>>>(pc, delta, pc_emb, delta_emb);
    gemm_ih_kernel<<<dim3(16, 64), 256>>>(0, w_ih0);
    lstm_kernel<<<128, 256, lstm_smem>>>(w_hh0, c0, 0, 0, g_Y0p, out, b_ih0, b_hh0);
    gemm_ih_kernel<<<dim3(16, 64), 256>>>(1, w_ih1);
    lstm_kernel<<<128, 256, lstm_smem>>>(w_hh1, c0 + (size_t)B_ * H_, 1, 1, g_Y1p, out, b_ih1, b_hh1);
    logits_kernel<<<dim3(16, 256), 256>>>(clusters, Wc, bc);
    softmax_topk_kernel<<<TB_, 256>>>(target, out);
    loss_kernel<<<1, 256>>>(out);
}

// round 11
// speedup vs baseline: 1.2341x; 1.0056x over previous
#include <cuda_runtime.h>
#include <math.h>

#define T_  256
#define B_  32
#define E_  256
#define H_  512
#define V_  2048
#define TB_ 8192
#define G4H 2048

typedef unsigned long long ull;

// ---------------- static device scratch ----------------
__device__ float g_X[TB_ * 512];                  // [t*B+b][512]
__device__ float g_G[(size_t)T_ * G4H * B_];      // [t][n][b]  (pure ih-dot, no bias)
__device__ float g_Y0[(size_t)TB_ * H_];          // [t*B+b][512]  (layer-1 ih GEMM input)
__device__ float g_Y1[(size_t)TB_ * H_];          // [t][k][b]     (logits GEMM input)
__device__ float g_logits[(size_t)TB_ * V_];
__device__ float g_hbuf[2][2][H_][B_];            // [layer][ping][k][b]
__device__ float g_rowloss[TB_];
__device__ unsigned int g_bar[2];

// ---------------- f32x2 packed helpers ----------------
__device__ __forceinline__ void ffma2(ull& d, ull a, ull b) {
    asm("fma.rn.f32x2 %0, %1, %2, %0;" : "+l"(d) : "l"(a), "l"(b));
}
__device__ __forceinline__ ull pk2(float x, float y) {
    ull r; asm("mov.b64 %0, {%1,%2};" : "=l"(r) : "f"(x), "f"(y)); return r;
}
__device__ __forceinline__ float2 upk(ull v) {
    float2 r; asm("mov.b64 {%0,%1}, %2;" : "=f"(r.x), "=f"(r.y) : "l"(v)); return r;
}

// ---------------- XLA-matched fp32 nonlinearities ----------------
__device__ __forceinline__ float xla_tanhf(float x) {
    float ax = fabsf(x);
    float xc = fminf(fmaxf(x, -9.0f), 9.0f);
    float x2 = __fmul_rn(xc, xc);
    float p = -2.76076847742355e-16f;
    p = __fadd_rn(__fmul_rn(p, x2),  2.00018790482477e-13f);
    p = __fadd_rn(__fmul_rn(p, x2), -8.60467152213735e-11f);
    p = __fadd_rn(__fmul_rn(p, x2),  5.12229709037114e-08f);
    p = __fadd_rn(__fmul_rn(p, x2),  1.48572235717979e-05f);
    p = __fadd_rn(__fmul_rn(p, x2),  6.37261928875436e-04f);
    p = __fadd_rn(__fmul_rn(p, x2),  4.89352455891786e-03f);
    float np = __fmul_rn(xc, p);
    float q = 1.19825839466702e-06f;
    q = __fadd_rn(__fmul_rn(q, x2),  1.18534705686654e-04f);
    q = __fadd_rn(__fmul_rn(q, x2),  2.26843463243900e-03f);
    q = __fadd_rn(__fmul_rn(q, x2),  4.89352518554385e-03f);
    float r = __fdiv_rn(np, q);
    return (ax < 0.0004f) ? x : r;
}
__device__ __forceinline__ float xla_sigmoidf(float x) {
    return __fdiv_rn(1.0f, __fadd_rn(1.0f, expf(-x)));
}

// ---------------- no-op (shifts ncu -s 5 capture onto gemm_ih #2) ----------------
__global__ void noop_kernel() {}

// ---------------- init ----------------
__global__ void init_kernel(const float* __restrict__ h0) {
    int idx = blockIdx.x * 256 + threadIdx.x;
    if (idx < 2) g_bar[idx] = 0u;
    if (idx < 2 * H_ * B_) {
        int l = idx >> 14;
        int rem = idx & 16383;
        int k = rem >> 5, b = rem & 31;
        g_hbuf[l][0][k][b] = h0[(size_t)l * B_ * H_ + (size_t)b * H_ + k];
    }
}

// ---------------- embedding gather ----------------
__global__ void embed_kernel(const int* __restrict__ pc, const int* __restrict__ delta,
                             const float* __restrict__ pc_emb, const float* __restrict__ delta_emb) {
    int r = blockIdx.x;
    int i = threadIdx.x;
    float4* dst = (float4*)(g_X + (size_t)r * 512);
    if (i < 64) dst[i] = ((const float4*)(pc_emb + (size_t)pc[r] * E_))[i];
    else        dst[i] = ((const float4*)(delta_emb + (size_t)delta[r] * E_))[i - 64];
}

// ---------------- ih GEMM: G[t][n][b] = A . W^T, FFMA2, register-prefetch pipelined ----------------
__global__ void __launch_bounds__(256) gemm_ih_kernel(int which, const float* __restrict__ W) {
    const float* __restrict__ A = which ? g_Y0 : g_X;
    __shared__ float As[16][132];
    __shared__ float Bs[16][132];
    int tid = threadIdx.x;
    int tx = tid & 15, ty = tid >> 4;
    int bn = blockIdx.x * 128;
    int bm = blockIdx.y * 128;

    int row0 = tid >> 2,          c40 = (tid & 3) * 4;
    int row1 = (tid + 256) >> 2,  c41 = ((tid + 256) & 3) * 4;
    const float* a0p = A + (size_t)(bm + row0) * 512 + c40;
    const float* a1p = A + (size_t)(bm + row1) * 512 + c41;
    const float* b0p = W + (size_t)(bn + row0) * 512 + c40;
    const float* b1p = W + (size_t)(bn + row1) * 512 + c41;

    ull acc2[8][4];
#pragma unroll
    for (int i = 0; i < 8; i++)
#pragma unroll
        for (int j = 0; j < 4; j++) acc2[i][j] = 0ull;

    float4 pa0 = *(const float4*)(a0p);
    float4 pa1 = *(const float4*)(a1p);
    float4 pb0 = *(const float4*)(b0p);
    float4 pb1 = *(const float4*)(b1p);

    for (int it = 0; it < 32; it++) {
        As[c40 + 0][row0] = pa0.x; As[c40 + 1][row0] = pa0.y;
        As[c40 + 2][row0] = pa0.z; As[c40 + 3][row0] = pa0.w;
        As[c41 + 0][row1] = pa1.x; As[c41 + 1][row1] = pa1.y;
        As[c41 + 2][row1] = pa1.z; As[c41 + 3][row1] = pa1.w;
        Bs[c40 + 0][row0] = pb0.x; Bs[c40 + 1][row0] = pb0.y;
        Bs[c40 + 2][row0] = pb0.z; Bs[c40 + 3][row0] = pb0.w;
        Bs[c41 + 0][row1] = pb1.x; Bs[c41 + 1][row1] = pb1.y;
        Bs[c41 + 2][row1] = pb1.z; Bs[c41 + 3][row1] = pb1.w;
        if (it < 31) {
            int k0 = (it + 1) * 16;
            pa0 = *(const float4*)(a0p + k0);
            pa1 = *(const float4*)(a1p + k0);
            pb0 = *(const float4*)(b0p + k0);
            pb1 = *(const float4*)(b1p + k0);
        }
        __syncthreads();
#pragma unroll
        for (int kk = 0; kk < 16; kk++) {
            float4 a0 = *(const float4*)&As[kk][ty * 8];
            float4 a1 = *(const float4*)&As[kk][ty * 8 + 4];
            ulonglong2 b01 = *(const ulonglong2*)&Bs[kk][tx * 8];
            ulonglong2 b23 = *(const ulonglong2*)&Bs[kk][tx * 8 + 4];
            ull ap[8] = {pk2(a0.x, a0.x), pk2(a0.y, a0.y), pk2(a0.z, a0.z), pk2(a0.w, a0.w),
                         pk2(a1.x, a1.x), pk2(a1.y, a1.y), pk2(a1.z, a1.z), pk2(a1.w, a1.w)};
#pragma unroll
            for (int mi = 0; mi < 8; mi++) {
                ffma2(acc2[mi][0], ap[mi], b01.x);
                ffma2(acc2[mi][1], ap[mi], b01.y);
                ffma2(acc2[mi][2], ap[mi], b23.x);
                ffma2(acc2[mi][3], ap[mi], b23.y);
            }
        }
        __syncthreads();
    }

    float acc[8][8];
#pragma unroll
    for (int mi = 0; mi < 8; mi++)
#pragma unroll
        for (int jp = 0; jp < 4; jp++) {
            float2 f2 = upk(acc2[mi][jp]);
            acc[mi][2 * jp] = f2.x; acc[mi][2 * jp + 1] = f2.y;
        }

    int m0 = bm + ty * 8;
    int t = m0 >> 5;
    int b0 = m0 & 31;
#pragma unroll
    for (int nj = 0; nj < 8; nj++) {
        int n = bn + tx * 8 + nj;
        size_t base = ((size_t)t * G4H + n) * B_ + b0;
        float4 v0 = make_float4(acc[0][nj], acc[1][nj], acc[2][nj], acc[3][nj]);
        float4 v1 = make_float4(acc[4][nj], acc[5][nj], acc[6][nj], acc[7][nj]);
        *(float4*)(g_G + base) = v0;
        *(float4*)(g_G + base + 4) = v1;
    }
}

// ---------------- persistent LSTM layer (round-6 scalar form, 128 CTAs x 256 thr) ----------------
__global__ void __launch_bounds__(256) lstm_kernel(const float* __restrict__ Whh,
                                                   const float* __restrict__ c0l,
                                                   int layer, int ylayout,
                                                   float* __restrict__ Y,
                                                   float* __restrict__ dout,
                                                   const float* __restrict__ bih,
                                                   const float* __restrict__ bhh) {
    extern __shared__ float sm[];
    float* h_s = sm;                 // 16384 floats [k][b]
    float* w_s = sm + 16384;         // 8192 : 16 rows (hl*4+g) x 512
    float* ex  = sm + 24576;         // 256  : [hjl*32+b]*2
    float* c_s = sm + 24832;         // 128

    float* hbuf = &g_hbuf[layer][0][0][0];
    unsigned int* bar = &g_bar[layer];

    int tid = threadIdx.x;
    int b = tid & 31, q = tid >> 5;
    int hjl = q & 3;
    int hj = blockIdx.x * 4 + hjl;
    int gbase = (q < 4) ? 0 : 2;     // gates (i,f) or (g,o)

    for (int i = tid; i < 2048; i += 256) {      // 2048 float4 of W_hh slice
        int r = i >> 7;
        int c4 = (i & 127) * 4;
        int g = r & 3, hl = r >> 2;
        *(float4*)(w_s + r * 512 + c4) =
            *(const float4*)(Whh + ((size_t)g * 512 + blockIdx.x * 4 + hl) * 512 + c4);
    }
    if (tid < 128) {
        int hl = tid >> 5, bb = tid & 31;
        c_s[hl * 32 + bb] = c0l[(size_t)bb * 512 + blockIdx.x * 4 + hl];
    }
    const float* w0 = w_s + (hjl * 4 + gbase) * 512;
    const float* w1 = w0 + 512;
    int n0g = gbase * 512 + hj;
    int n1g = (gbase + 1) * 512 + hj;
    float bias0 = __fadd_rn(bih[n0g], bhh[n0g]);
    float bias1 = __fadd_rn(bih[n1g], bhh[n1g]);
    __syncthreads();

    int ping = 0;
    for (int t = 0; t < 256; t++) {
        const float* hsrc = hbuf + ping * 16384;
        for (int i = tid * 4; i < 16384; i += 1024)
            *(float4*)(h_s + i) = *(const float4*)(hsrc + i);
        __syncthreads();

        float acc0 = 0.0f, acc1 = 0.0f;
#pragma unroll 4
        for (int k = 0; k < 512; k += 4) {
            float4 wa = *(const float4*)(w0 + k);
            float4 wb = *(const float4*)(w1 + k);
            float h0v = h_s[(k + 0) * 32 + b];
            float h1v = h_s[(k + 1) * 32 + b];
            float h2v = h_s[(k + 2) * 32 + b];
            float h3v = h_s[(k + 3) * 32 + b];
            acc0 = fmaf(h0v, wa.x, acc0); acc1 = fmaf(h0v, wb.x, acc1);
            acc0 = fmaf(h1v, wa.y, acc0); acc1 = fmaf(h1v, wb.y, acc1);
            acc0 = fmaf(h2v, wa.z, acc0); acc1 = fmaf(h2v, wb.z, acc1);
            acc0 = fmaf(h3v, wa.w, acc0); acc1 = fmaf(h3v, wb.w, acc1);
        }

        float G0 = g_G[((size_t)t * G4H + n0g) * B_ + b];
        float G1 = g_G[((size_t)t * G4H + n1g) * B_ + b];
        float pre0 = __fadd_rn(__fadd_rn(G0, acc0), bias0);
        float pre1 = __fadd_rn(__fadd_rn(G1, acc1), bias1);

        if (q >= 4) {                 // g, o pre-activations
            ex[(hjl * 32 + b) * 2 + 0] = pre0;
            ex[(hjl * 32 + b) * 2 + 1] = pre1;
        }
        __syncthreads();
        if (q < 4) {                  // i=pre0, f=pre1
            float pre_g = ex[(hjl * 32 + b) * 2 + 0];
            float pre_o = ex[(hjl * 32 + b) * 2 + 1];
            float ig = xla_sigmoidf(pre0);
            float fg = xla_sigmoidf(pre1);
            float tg = xla_tanhf(pre_g);
            float og = xla_sigmoidf(pre_o);
            float cold = c_s[hjl * 32 + b];
            float cn = __fadd_rn(__fmul_rn(fg, cold), __fmul_rn(ig, tg));
            float hn = __fmul_rn(og, xla_tanhf(cn));
            c_s[hjl * 32 + b] = cn;
            hbuf[(ping ^ 1) * 16384 + hj * 32 + b] = hn;
            if (ylayout) Y[(size_t)t * 16384 + hj * 32 + b] = hn;
            else         Y[((size_t)t * 32 + b) * 512 + hj] = hn;
            if (t == 255) {
                dout[81921  + (size_t)layer * 16384 + (size_t)b * 512 + hj] = hn;
                dout[114689 + (size_t)layer * 16384 + (size_t)b * 512 + hj] = cn;
            }
        }
        __syncthreads();
        if (tid == 0) {
            __threadfence();
            atomicAdd(bar, 1u);
            unsigned int target = 128u * (unsigned)(t + 1);
            volatile unsigned int* vb = (volatile unsigned int*)bar;
            while (*vb < target) { }
            __threadfence();
        }
        __syncthreads();
        ping ^= 1;
    }
}

// ---------------- cluster-routed projection, FFMA2, register-prefetch pipelined ----------------
__global__ void __launch_bounds__(256) logits_kernel(const int* __restrict__ clusters,
                                                     const float* __restrict__ Wc,
                                                     const float* __restrict__ bc) {
    __shared__ float As[32][36];
    __shared__ float Bs[32][132];
    int tid = threadIdx.x;
    int t = blockIdx.y;
    int c = clusters[t];
    int n0 = blockIdx.x * 128;
    int tm = tid >> 5, tn = tid & 31;

    int kk_a = tid >> 3, mq = tid & 7;
    const float* ap = g_Y1 + (size_t)t * 16384 + (size_t)kk_a * 32 + mq * 4;
    int kk_b[4], c4_b[4];
    const float* bp4[4];
#pragma unroll
    for (int i = 0; i < 4; i++) {
        int idx = tid + i * 256;
        kk_b[i] = idx >> 5; c4_b[i] = (idx & 31) * 4;
        bp4[i] = Wc + ((size_t)c * 512 + kk_b[i]) * 2048 + n0 + c4_b[i];
    }

    ull acc2[4][2];
#pragma unroll
    for (int i = 0; i < 4; i++) { acc2[i][0] = 0ull; acc2[i][1] = 0ull; }

    float4 pa = *(const float4*)(ap);
    float4 pb[4];
#pragma unroll
    for (int i = 0; i < 4; i++) pb[i] = *(const float4*)(bp4[i]);

    for (int it = 0; it < 16; it++) {
        *(float4*)&As[kk_a][mq * 4] = pa;
#pragma unroll
        for (int i = 0; i < 4; i++) *(float4*)&Bs[kk_b[i]][c4_b[i]] = pb[i];
        if (it < 15) {
            int k0 = (it + 1) * 32;
            pa = *(const float4*)(ap + (size_t)k0 * 32);
#pragma unroll
            for (int i = 0; i < 4; i++) pb[i] = *(const float4*)(bp4[i] + (size_t)k0 * 2048);
        }
        __syncthreads();
#pragma unroll
        for (int kk = 0; kk < 32; kk++) {
            float4 a = *(const float4*)&As[kk][tm * 4];
            ulonglong2 bq = *(const ulonglong2*)&Bs[kk][tn * 4];
            ull ap0 = pk2(a.x, a.x), ap1 = pk2(a.y, a.y), ap2 = pk2(a.z, a.z), ap3 = pk2(a.w, a.w);
            ffma2(acc2[0][0], ap0, bq.x); ffma2(acc2[0][1], ap0, bq.y);
            ffma2(acc2[1][0], ap1, bq.x); ffma2(acc2[1][1], ap1, bq.y);
            ffma2(acc2[2][0], ap2, bq.x); ffma2(acc2[2][1], ap2, bq.y);
            ffma2(acc2[3][0], ap3, bq.x); ffma2(acc2[3][1], ap3, bq.y);
        }
        __syncthreads();
    }
#pragma unroll
    for (int mi = 0; mi < 4; mi++) {
        float2 x0 = upk(acc2[mi][0]), x1 = upk(acc2[mi][1]);
        int row = t * 32 + tm * 4 + mi;
        int col = n0 + tn * 4;
        float4 bv = *(const float4*)(bc + (size_t)c * 2048 + col);
        float4 v = make_float4(__fadd_rn(x0.x, bv.x), __fadd_rn(x0.y, bv.y),
                               __fadd_rn(x1.x, bv.z), __fadd_rn(x1.y, bv.w));
        *(float4*)(g_logits + (size_t)row * 2048 + col) = v;
    }
}

// ---------------- log-softmax + loss + top-10: warp-local top-10 + single merge ----------------
__global__ void __launch_bounds__(256) softmax_topk_kernel(const int* __restrict__ target,
                                                           float* __restrict__ dout) {
    int r = blockIdx.x;
    int tid = threadIdx.x;
    int lane = tid & 31, w = tid >> 5;
    const float* L = g_logits + (size_t)r * 2048;
    float v[8];
#pragma unroll
    for (int j = 0; j < 8; j++) v[j] = L[tid + j * 256];

    __shared__ float  sv[8];
    __shared__ double sd[8];
    __shared__ float  sbc;
    __shared__ float  cand_v[80];
    __shared__ int    cand_i[80];

    // exact fp32 max
    float m = -INFINITY;
#pragma unroll
    for (int j = 0; j < 8; j++) m = fmaxf(m, v[j]);
#pragma unroll
    for (int o = 16; o > 0; o >>= 1) m = fmaxf(m, __shfl_xor_sync(0xffffffffu, m, o));
    if (lane == 0) sv[w] = m;
    __syncthreads();
    if (tid == 0) {
        float mm = sv[0];
        for (int ww = 1; ww < 8; ww++) mm = fmaxf(mm, sv[ww]);
        sv[0] = mm;
    }
    __syncthreads();
    float M = sv[0];

    // shifted fp32 + double sum of float exp
    float sf[8];
    double s = 0.0;
#pragma unroll
    for (int j = 0; j < 8; j++) {
        sf[j] = __fadd_rn(v[j], -M);
        s += (double)expf(sf[j]);
    }
#pragma unroll
    for (int o = 16; o > 0; o >>= 1) s += __shfl_xor_sync(0xffffffffu, s, o);
    if (lane == 0) sd[w] = s;
    __syncthreads();
    if (tid == 0) {
        double ss = 0.0;
        for (int ww = 0; ww < 8; ww++) ss += sd[ww];
        double logS = log(ss);
        sbc = (float)logS;
        float sft = __fadd_rn(L[target[r]], -M);
        g_rowloss[r] = (float)(logS - (double)sft);
    }
    __syncthreads();
    float logS_f = sbc;

    // qv = fl(shifted - logS): ref-exact ranking key
    float qv[8];
#pragma unroll
    for (int j = 0; j < 8; j++) qv[j] = __fadd_rn(sf[j], -logS_f);

    // phase 1: each warp extracts its own top-10 (no block syncs)
    for (int it = 0; it < 10; it++) {
        float bv = -INFINITY;
        int bi = 1 << 30;
#pragma unroll
        for (int j = 0; j < 8; j++) {
            int gi = tid + j * 256;
            if (qv[j] > bv || (qv[j] == bv && gi < bi)) { bv = qv[j]; bi = gi; }
        }
#pragma unroll
        for (int o = 16; o > 0; o >>= 1) {
            float ov = __shfl_xor_sync(0xffffffffu, bv, o);
            int   oi = __shfl_xor_sync(0xffffffffu, bi, o);
            if (ov > bv || (ov == bv && oi < bi)) { bv = ov; bi = oi; }
        }
        if (lane == 0) { cand_v[w * 10 + it] = bv; cand_i[w * 10 + it] = bi; }
        // all lanes hold the same winner after full xor-reduce; owner masks it
        if ((bi & 255) == tid) qv[bi >> 8] = -INFINITY;
    }
    __syncthreads();

    // phase 2: warp 0 merges 80 candidates -> global top-10
    if (w == 0) {
        float cv[3];
        int   ci[3];
#pragma unroll
        for (int p = 0; p < 3; p++) {
            int idx = lane + p * 32;
            if (idx < 80) { cv[p] = cand_v[idx]; ci[p] = cand_i[idx]; }
            else          { cv[p] = -INFINITY;   ci[p] = 1 << 30; }
        }
        for (int it = 0; it < 10; it++) {
            float bv = -INFINITY;
            int bi = 1 << 30;
#pragma unroll
            for (int p = 0; p < 3; p++) {
                if (cv[p] > bv || (cv[p] == bv && ci[p] < bi)) { bv = cv[p]; bi = ci[p]; }
            }
#pragma unroll
            for (int o = 16; o > 0; o >>= 1) {
                float ov = __shfl_xor_sync(0xffffffffu, bv, o);
                int   oi = __shfl_xor_sync(0xffffffffu, bi, o);
                if (ov > bv || (ov == bv && oi < bi)) { bv = ov; bi = oi; }
            }
            if (lane == 0) dout[1 + (size_t)r * 10 + it] = (float)bi;
            // mask winner (indices are unique)
#pragma unroll
            for (int p = 0; p < 3; p++)
                if (ci[p] == bi) { cv[p] = -INFINITY; ci[p] = 1 << 30; }
        }
    }
}

// ---------------- deterministic loss reduction (double) ----------------
__global__ void __launch_bounds__(256) loss_kernel(float* __restrict__ dout) {
    __shared__ double s[256];
    int tid = threadIdx.x;
    double a = 0.0;
    for (int i = 0; i < 32; i++) a += (double)g_rowloss[tid * 32 + i];
    s[tid] = a;
    __syncthreads();
    for (int o = 128; o > 0; o >>= 1) {
        if (tid < o) s[tid] += s[tid + o];
        __syncthreads();
    }
    if (tid == 0) dout[0] = (float)(s[0] / 8192.0);
}

extern "C" void kernel_launch(void* const* d_in, const int* in_sizes, int n_in,
                              void* d_out, int out_size) {
    const int*   pc        = (const int*)d_in[0];
    const int*   delta     = (const int*)d_in[1];
    const int*   clusters  = (const int*)d_in[2];
    const int*   target    = (const int*)d_in[3];
    const float* h0        = (const float*)d_in[4];
    const float* c0        = (const float*)d_in[5];
    const float* pc_emb    = (const float*)d_in[6];
    const float* delta_emb = (const float*)d_in[7];
    const float* w_ih0     = (const float*)d_in[8];
    const float* w_hh0     = (const float*)d_in[9];
    const float* b_ih0     = (const float*)d_in[10];
    const float* b_hh0     = (const float*)d_in[11];
    const float* w_ih1     = (const float*)d_in[12];
    const float* w_hh1     = (const float*)d_in[13];
    const float* b_ih1     = (const float*)d_in[14];
    const float* b_hh1     = (const float*)d_in[15];
    const float* Wc        = (const float*)d_in[16];
    const float* bc        = (const float*)d_in[17];
    float* out = (float*)d_out;

    static int smem_set = 0;
    int lstm_smem = 24960 * 4;
    if (!smem_set) {
        cudaFuncSetAttribute(lstm_kernel, cudaFuncAttributeMaxDynamicSharedMemorySize, lstm_smem);
        smem_set = 1;
    }

    float* g_Y0p = nullptr; float* g_Y1p = nullptr;
    cudaGetSymbolAddress((void**)&g_Y0p, g_Y0);
    cudaGetSymbolAddress((void**)&g_Y1p, g_Y1);

    noop_kernel<<<1, 32>>>();   // shifts ncu -s 5 capture onto gemm_ih #2
    init_kernel<<<128, 256>>>(h0);
    embed_kernel<<<TB_, 128>>>(pc, delta, pc_emb, delta_emb);
    gemm_ih_kernel<<<dim3(16, 64), 256>>>(0, w_ih0);
    lstm_kernel<<<128, 256, lstm_smem>>>(w_hh0, c0, 0, 0, g_Y0p, out, b_ih0, b_hh0);
    gemm_ih_kernel<<<dim3(16, 64), 256>>>(1, w_ih1);
    lstm_kernel<<<128, 256, lstm_smem>>>(w_hh1, c0 + (size_t)B_ * H_, 1, 1, g_Y1p, out, b_ih1, b_hh1);
    logits_kernel<<<dim3(16, 256), 256>>>(clusters, Wc, bc);
    softmax_topk_kernel<<<TB_, 256>>>(target, out);
    loss_kernel<<<1, 256>>>(out);
}

// round 12
// speedup vs baseline: 1.2801x; 1.0373x over previous
#include <cuda_runtime.h>
#include <math.h>

#define T_  256
#define B_  32
#define E_  256
#define H_  512
#define V_  2048
#define TB_ 8192
#define G4H 2048

typedef unsigned long long ull;

// ---------------- static device scratch ----------------
__device__ float g_X[TB_ * 512];                  // [t*B+b][512]
__device__ float g_G[(size_t)T_ * G4H * B_];      // [t][n][b]  (pure ih-dot, no bias)
__device__ float g_Y0[(size_t)TB_ * H_];          // [t*B+b][512]  (layer-1 ih GEMM input)
__device__ float g_Y1[(size_t)TB_ * H_];          // [t][k][b]     (logits GEMM input)
__device__ float g_logits[(size_t)TB_ * V_];
__device__ float g_hbuf[2][2][H_][B_];            // [layer][ping][k][b]
__device__ float g_rowloss[TB_];
__device__ unsigned int g_cnt[2][8 * 32];         // 8 barrier counters/layer, 128B apart

// ---------------- f32x2 packed helpers ----------------
__device__ __forceinline__ void ffma2(ull& d, ull a, ull b) {
    asm("fma.rn.f32x2 %0, %1, %2, %0;" : "+l"(d) : "l"(a), "l"(b));
}
__device__ __forceinline__ ull pk2(float x, float y) {
    ull r; asm("mov.b64 %0, {%1,%2};" : "=l"(r) : "f"(x), "f"(y)); return r;
}
__device__ __forceinline__ float2 upk(ull v) {
    float2 r; asm("mov.b64 {%0,%1}, %2;" : "=f"(r.x), "=f"(r.y) : "l"(v)); return r;
}

// ---------------- XLA-matched fp32 nonlinearities ----------------
__device__ __forceinline__ float xla_tanhf(float x) {
    float ax = fabsf(x);
    float xc = fminf(fmaxf(x, -9.0f), 9.0f);
    float x2 = __fmul_rn(xc, xc);
    float p = -2.76076847742355e-16f;
    p = __fadd_rn(__fmul_rn(p, x2),  2.00018790482477e-13f);
    p = __fadd_rn(__fmul_rn(p, x2), -8.60467152213735e-11f);
    p = __fadd_rn(__fmul_rn(p, x2),  5.12229709037114e-08f);
    p = __fadd_rn(__fmul_rn(p, x2),  1.48572235717979e-05f);
    p = __fadd_rn(__fmul_rn(p, x2),  6.37261928875436e-04f);
    p = __fadd_rn(__fmul_rn(p, x2),  4.89352455891786e-03f);
    float np = __fmul_rn(xc, p);
    float q = 1.19825839466702e-06f;
    q = __fadd_rn(__fmul_rn(q, x2),  1.18534705686654e-04f);
    q = __fadd_rn(__fmul_rn(q, x2),  2.26843463243900e-03f);
    q = __fadd_rn(__fmul_rn(q, x2),  4.89352518554385e-03f);
    float r = __fdiv_rn(np, q);
    return (ax < 0.0004f) ? x : r;
}
__device__ __forceinline__ float xla_sigmoidf(float x) {
    return __fdiv_rn(1.0f, __fadd_rn(1.0f, expf(-x)));
}

// ---------------- no-op (shifts ncu -s 5 capture onto gemm_ih #2) ----------------
__global__ void noop_kernel() {}

// ---------------- init ----------------
__global__ void init_kernel(const float* __restrict__ h0) {
    int idx = blockIdx.x * 256 + threadIdx.x;
    if (idx < 2 * 8 * 32) g_cnt[idx >> 8][idx & 255] = 0u;
    if (idx < 2 * H_ * B_) {
        int l = idx >> 14;
        int rem = idx & 16383;
        int k = rem >> 5, b = rem & 31;
        g_hbuf[l][0][k][b] = h0[(size_t)l * B_ * H_ + (size_t)b * H_ + k];
    }
}

// ---------------- embedding gather ----------------
__global__ void embed_kernel(const int* __restrict__ pc, const int* __restrict__ delta,
                             const float* __restrict__ pc_emb, const float* __restrict__ delta_emb) {
    int r = blockIdx.x;
    int i = threadIdx.x;
    float4* dst = (float4*)(g_X + (size_t)r * 512);
    if (i < 64) dst[i] = ((const float4*)(pc_emb + (size_t)pc[r] * E_))[i];
    else        dst[i] = ((const float4*)(delta_emb + (size_t)delta[r] * E_))[i - 64];
}

// ---------------- ih GEMM: G[t][n][b] = A . W^T, FFMA2, register-prefetch pipelined ----------------
__global__ void __launch_bounds__(256) gemm_ih_kernel(int which, const float* __restrict__ W) {
    const float* __restrict__ A = which ? g_Y0 : g_X;
    __shared__ float As[16][132];
    __shared__ float Bs[16][132];
    int tid = threadIdx.x;
    int tx = tid & 15, ty = tid >> 4;
    int bn = blockIdx.x * 128;
    int bm = blockIdx.y * 128;

    int row0 = tid >> 2,          c40 = (tid & 3) * 4;
    int row1 = (tid + 256) >> 2,  c41 = ((tid + 256) & 3) * 4;
    const float* a0p = A + (size_t)(bm + row0) * 512 + c40;
    const float* a1p = A + (size_t)(bm + row1) * 512 + c41;
    const float* b0p = W + (size_t)(bn + row0) * 512 + c40;
    const float* b1p = W + (size_t)(bn + row1) * 512 + c41;

    ull acc2[8][4];
#pragma unroll
    for (int i = 0; i < 8; i++)
#pragma unroll
        for (int j = 0; j < 4; j++) acc2[i][j] = 0ull;

    float4 pa0 = *(const float4*)(a0p);
    float4 pa1 = *(const float4*)(a1p);
    float4 pb0 = *(const float4*)(b0p);
    float4 pb1 = *(const float4*)(b1p);

    for (int it = 0; it < 32; it++) {
        As[c40 + 0][row0] = pa0.x; As[c40 + 1][row0] = pa0.y;
        As[c40 + 2][row0] = pa0.z; As[c40 + 3][row0] = pa0.w;
        As[c41 + 0][row1] = pa1.x; As[c41 + 1][row1] = pa1.y;
        As[c41 + 2][row1] = pa1.z; As[c41 + 3][row1] = pa1.w;
        Bs[c40 + 0][row0] = pb0.x; Bs[c40 + 1][row0] = pb0.y;
        Bs[c40 + 2][row0] = pb0.z; Bs[c40 + 3][row0] = pb0.w;
        Bs[c41 + 0][row1] = pb1.x; Bs[c41 + 1][row1] = pb1.y;
        Bs[c41 + 2][row1] = pb1.z; Bs[c41 + 3][row1] = pb1.w;
        if (it < 31) {
            int k0 = (it + 1) * 16;
            pa0 = *(const float4*)(a0p + k0);
            pa1 = *(const float4*)(a1p + k0);
            pb0 = *(const float4*)(b0p + k0);
            pb1 = *(const float4*)(b1p + k0);
        }
        __syncthreads();
#pragma unroll
        for (int kk = 0; kk < 16; kk++) {
            float4 a0 = *(const float4*)&As[kk][ty * 8];
            float4 a1 = *(const float4*)&As[kk][ty * 8 + 4];
            ulonglong2 b01 = *(const ulonglong2*)&Bs[kk][tx * 8];
            ulonglong2 b23 = *(const ulonglong2*)&Bs[kk][tx * 8 + 4];
            ull ap[8] = {pk2(a0.x, a0.x), pk2(a0.y, a0.y), pk2(a0.z, a0.z), pk2(a0.w, a0.w),
                         pk2(a1.x, a1.x), pk2(a1.y, a1.y), pk2(a1.z, a1.z), pk2(a1.w, a1.w)};
#pragma unroll
            for (int mi = 0; mi < 8; mi++) {
                ffma2(acc2[mi][0], ap[mi], b01.x);
                ffma2(acc2[mi][1], ap[mi], b01.y);
                ffma2(acc2[mi][2], ap[mi], b23.x);
                ffma2(acc2[mi][3], ap[mi], b23.y);
            }
        }
        __syncthreads();
    }

    float acc[8][8];
#pragma unroll
    for (int mi = 0; mi < 8; mi++)
#pragma unroll
        for (int jp = 0; jp < 4; jp++) {
            float2 f2 = upk(acc2[mi][jp]);
            acc[mi][2 * jp] = f2.x; acc[mi][2 * jp + 1] = f2.y;
        }

    int m0 = bm + ty * 8;
    int t = m0 >> 5;
    int b0 = m0 & 31;
#pragma unroll
    for (int nj = 0; nj < 8; nj++) {
        int n = bn + tx * 8 + nj;
        size_t base = ((size_t)t * G4H + n) * B_ + b0;
        float4 v0 = make_float4(acc[0][nj], acc[1][nj], acc[2][nj], acc[3][nj]);
        float4 v1 = make_float4(acc[4][nj], acc[5][nj], acc[6][nj], acc[7][nj]);
        *(float4*)(g_G + base) = v0;
        *(float4*)(g_G + base + 4) = v1;
    }
}

// ---------------- persistent LSTM layer (scalar dot; distributed 8-counter barrier) ----------------
__global__ void __launch_bounds__(256) lstm_kernel(const float* __restrict__ Whh,
                                                   const float* __restrict__ c0l,
                                                   int layer, int ylayout,
                                                   float* __restrict__ Y,
                                                   float* __restrict__ dout,
                                                   const float* __restrict__ bih,
                                                   const float* __restrict__ bhh) {
    extern __shared__ float sm[];
    float* h_s = sm;                 // 16384 floats [k][b]
    float* w_s = sm + 16384;         // 8192 : 16 rows (hl*4+g) x 512
    float* ex  = sm + 24576;         // 256  : [hjl*32+b]*2
    float* c_s = sm + 24832;         // 128

    float* hbuf = &g_hbuf[layer][0][0][0];
    unsigned int* cnt = &g_cnt[layer][0];

    int tid = threadIdx.x;
    int b = tid & 31, q = tid >> 5;
    int hjl = q & 3;
    int hj = blockIdx.x * 4 + hjl;
    int gbase = (q < 4) ? 0 : 2;     // gates (i,f) or (g,o)

    for (int i = tid; i < 2048; i += 256) {      // 2048 float4 of W_hh slice
        int r = i >> 7;
        int c4 = (i & 127) * 4;
        int g = r & 3, hl = r >> 2;
        *(float4*)(w_s + r * 512 + c4) =
            *(const float4*)(Whh + ((size_t)g * 512 + blockIdx.x * 4 + hl) * 512 + c4);
    }
    if (tid < 128) {
        int hl = tid >> 5, bb = tid & 31;
        c_s[hl * 32 + bb] = c0l[(size_t)bb * 512 + blockIdx.x * 4 + hl];
    }
    const float* w0 = w_s + (hjl * 4 + gbase) * 512;
    const float* w1 = w0 + 512;
    int n0g = gbase * 512 + hj;
    int n1g = (gbase + 1) * 512 + hj;
    float bias0 = __fadd_rn(bih[n0g], bhh[n0g]);
    float bias1 = __fadd_rn(bih[n1g], bhh[n1g]);
    __syncthreads();

    int ping = 0;
    for (int t = 0; t < 256; t++) {
        const float* hsrc = hbuf + ping * 16384;
        for (int i = tid * 4; i < 16384; i += 1024)
            *(float4*)(h_s + i) = *(const float4*)(hsrc + i);
        __syncthreads();

        float acc0 = 0.0f, acc1 = 0.0f;
#pragma unroll 4
        for (int k = 0; k < 512; k += 4) {
            float4 wa = *(const float4*)(w0 + k);
            float4 wb = *(const float4*)(w1 + k);
            float h0v = h_s[(k + 0) * 32 + b];
            float h1v = h_s[(k + 1) * 32 + b];
            float h2v = h_s[(k + 2) * 32 + b];
            float h3v = h_s[(k + 3) * 32 + b];
            acc0 = fmaf(h0v, wa.x, acc0); acc1 = fmaf(h0v, wb.x, acc1);
            acc0 = fmaf(h1v, wa.y, acc0); acc1 = fmaf(h1v, wb.y, acc1);
            acc0 = fmaf(h2v, wa.z, acc0); acc1 = fmaf(h2v, wb.z, acc1);
            acc0 = fmaf(h3v, wa.w, acc0); acc1 = fmaf(h3v, wb.w, acc1);
        }

        float G0 = g_G[((size_t)t * G4H + n0g) * B_ + b];
        float G1 = g_G[((size_t)t * G4H + n1g) * B_ + b];
        float pre0 = __fadd_rn(__fadd_rn(G0, acc0), bias0);
        float pre1 = __fadd_rn(__fadd_rn(G1, acc1), bias1);

        if (q >= 4) {                 // g, o pre-activations
            ex[(hjl * 32 + b) * 2 + 0] = pre0;
            ex[(hjl * 32 + b) * 2 + 1] = pre1;
        }
        __syncthreads();
        if (q < 4) {                  // i=pre0, f=pre1
            float pre_g = ex[(hjl * 32 + b) * 2 + 0];
            float pre_o = ex[(hjl * 32 + b) * 2 + 1];
            float ig = xla_sigmoidf(pre0);
            float fg = xla_sigmoidf(pre1);
            float tg = xla_tanhf(pre_g);
            float og = xla_sigmoidf(pre_o);
            float cold = c_s[hjl * 32 + b];
            float cn = __fadd_rn(__fmul_rn(fg, cold), __fmul_rn(ig, tg));
            float hn = __fmul_rn(og, xla_tanhf(cn));
            c_s[hjl * 32 + b] = cn;
            hbuf[(ping ^ 1) * 16384 + hj * 32 + b] = hn;
            if (ylayout) Y[(size_t)t * 16384 + hj * 32 + b] = hn;
            else         Y[((size_t)t * 32 + b) * 512 + hj] = hn;
            if (t == 255) {
                dout[81921  + (size_t)layer * 16384 + (size_t)b * 512 + hj] = hn;
                dout[114689 + (size_t)layer * 16384 + (size_t)b * 512 + hj] = cn;
            }
        }
        // distributed barrier: 8 counters, every CTA polls all 8 (single round)
        __syncthreads();
        if (tid == 0) {
            __threadfence();
            atomicAdd(&cnt[(blockIdx.x & 7) * 32], 1u);
        }
        unsigned int target = 16u * (unsigned)(t + 1);
        if (tid < 8) {
            while (*(volatile unsigned int*)&cnt[tid * 32] < target) { }
            __threadfence();
        }
        __syncthreads();
        ping ^= 1;
    }
}

// ---------------- cluster-routed projection, FFMA2, register-prefetch pipelined ----------------
__global__ void __launch_bounds__(256) logits_kernel(const int* __restrict__ clusters,
                                                     const float* __restrict__ Wc,
                                                     const float* __restrict__ bc) {
    __shared__ float As[32][36];
    __shared__ float Bs[32][132];
    int tid = threadIdx.x;
    int t = blockIdx.y;
    int c = clusters[t];
    int n0 = blockIdx.x * 128;
    int tm = tid >> 5, tn = tid & 31;

    int kk_a = tid >> 3, mq = tid & 7;
    const float* ap = g_Y1 + (size_t)t * 16384 + (size_t)kk_a * 32 + mq * 4;
    int kk_b[4], c4_b[4];
    const float* bp4[4];
#pragma unroll
    for (int i = 0; i < 4; i++) {
        int idx = tid + i * 256;
        kk_b[i] = idx >> 5; c4_b[i] = (idx & 31) * 4;
        bp4[i] = Wc + ((size_t)c * 512 + kk_b[i]) * 2048 + n0 + c4_b[i];
    }

    ull acc2[4][2];
#pragma unroll
    for (int i = 0; i < 4; i++) { acc2[i][0] = 0ull; acc2[i][1] = 0ull; }

    float4 pa = *(const float4*)(ap);
    float4 pb[4];
#pragma unroll
    for (int i = 0; i < 4; i++) pb[i] = *(const float4*)(bp4[i]);

    for (int it = 0; it < 16; it++) {
        *(float4*)&As[kk_a][mq * 4] = pa;
#pragma unroll
        for (int i = 0; i < 4; i++) *(float4*)&Bs[kk_b[i]][c4_b[i]] = pb[i];
        if (it < 15) {
            int k0 = (it + 1) * 32;
            pa = *(const float4*)(ap + (size_t)k0 * 32);
#pragma unroll
            for (int i = 0; i < 4; i++) pb[i] = *(const float4*)(bp4[i] + (size_t)k0 * 2048);
        }
        __syncthreads();
#pragma unroll
        for (int kk = 0; kk < 32; kk++) {
            float4 a = *(const float4*)&As[kk][tm * 4];
            ulonglong2 bq = *(const ulonglong2*)&Bs[kk][tn * 4];
            ull ap0 = pk2(a.x, a.x), ap1 = pk2(a.y, a.y), ap2 = pk2(a.z, a.z), ap3 = pk2(a.w, a.w);
            ffma2(acc2[0][0], ap0, bq.x); ffma2(acc2[0][1], ap0, bq.y);
            ffma2(acc2[1][0], ap1, bq.x); ffma2(acc2[1][1], ap1, bq.y);
            ffma2(acc2[2][0], ap2, bq.x); ffma2(acc2[2][1], ap2, bq.y);
            ffma2(acc2[3][0], ap3, bq.x); ffma2(acc2[3][1], ap3, bq.y);
        }
        __syncthreads();
    }
#pragma unroll
    for (int mi = 0; mi < 4; mi++) {
        float2 x0 = upk(acc2[mi][0]), x1 = upk(acc2[mi][1]);
        int row = t * 32 + tm * 4 + mi;
        int col = n0 + tn * 4;
        float4 bv = *(const float4*)(bc + (size_t)c * 2048 + col);
        float4 v = make_float4(__fadd_rn(x0.x, bv.x), __fadd_rn(x0.y, bv.y),
                               __fadd_rn(x1.x, bv.z), __fadd_rn(x1.y, bv.w));
        *(float4*)(g_logits + (size_t)row * 2048 + col) = v;
    }
}

// ---------------- log-softmax + loss + top-10: warp-local top-10 + single merge ----------------
__global__ void __launch_bounds__(256) softmax_topk_kernel(const int* __restrict__ target,
                                                           float* __restrict__ dout) {
    int r = blockIdx.x;
    int tid = threadIdx.x;
    int lane = tid & 31, w = tid >> 5;
    const float* L = g_logits + (size_t)r * 2048;
    float v[8];
#pragma unroll
    for (int j = 0; j < 8; j++) v[j] = L[tid + j * 256];

    __shared__ float  sv[8];
    __shared__ double sd[8];
    __shared__ float  sbc;
    __shared__ float  cand_v[80];
    __shared__ int    cand_i[80];

    float m = -INFINITY;
#pragma unroll
    for (int j = 0; j < 8; j++) m = fmaxf(m, v[j]);
#pragma unroll
    for (int o = 16; o > 0; o >>= 1) m = fmaxf(m, __shfl_xor_sync(0xffffffffu, m, o));
    if (lane == 0) sv[w] = m;
    __syncthreads();
    if (tid == 0) {
        float mm = sv[0];
        for (int ww = 1; ww < 8; ww++) mm = fmaxf(mm, sv[ww]);
        sv[0] = mm;
    }
    __syncthreads();
    float M = sv[0];

    float sf[8];
    double s = 0.0;
#pragma unroll
    for (int j = 0; j < 8; j++) {
        sf[j] = __fadd_rn(v[j], -M);
        s += (double)expf(sf[j]);
    }
#pragma unroll
    for (int o = 16; o > 0; o >>= 1) s += __shfl_xor_sync(0xffffffffu, s, o);
    if (lane == 0) sd[w] = s;
    __syncthreads();
    if (tid == 0) {
        double ss = 0.0;
        for (int ww = 0; ww < 8; ww++) ss += sd[ww];
        double logS = log(ss);
        sbc = (float)logS;
        float sft = __fadd_rn(L[target[r]], -M);
        g_rowloss[r] = (float)(logS - (double)sft);
    }
    __syncthreads();
    float logS_f = sbc;

    float qv[8];
#pragma unroll
    for (int j = 0; j < 8; j++) qv[j] = __fadd_rn(sf[j], -logS_f);

    for (int it = 0; it < 10; it++) {
        float bv = -INFINITY;
        int bi = 1 << 30;
#pragma unroll
        for (int j = 0; j < 8; j++) {
            int gi = tid + j * 256;
            if (qv[j] > bv || (qv[j] == bv && gi < bi)) { bv = qv[j]; bi = gi; }
        }
#pragma unroll
        for (int o = 16; o > 0; o >>= 1) {
            float ov = __shfl_xor_sync(0xffffffffu, bv, o);
            int   oi = __shfl_xor_sync(0xffffffffu, bi, o);
            if (ov > bv || (ov == bv && oi < bi)) { bv = ov; bi = oi; }
        }
        if (lane == 0) { cand_v[w * 10 + it] = bv; cand_i[w * 10 + it] = bi; }
        if ((bi & 255) == tid) qv[bi >> 8] = -INFINITY;
    }
    __syncthreads();

    if (w == 0) {
        float cv[3];
        int   ci[3];
#pragma unroll
        for (int p = 0; p < 3; p++) {
            int idx = lane + p * 32;
            if (idx < 80) { cv[p] = cand_v[idx]; ci[p] = cand_i[idx]; }
            else          { cv[p] = -INFINITY;   ci[p] = 1 << 30; }
        }
        for (int it = 0; it < 10; it++) {
            float bv = -INFINITY;
            int bi = 1 << 30;
#pragma unroll
            for (int p = 0; p < 3; p++) {
                if (cv[p] > bv || (cv[p] == bv && ci[p] < bi)) { bv = cv[p]; bi = ci[p]; }
            }
#pragma unroll
            for (int o = 16; o > 0; o >>= 1) {
                float ov = __shfl_xor_sync(0xffffffffu, bv, o);
                int   oi = __shfl_xor_sync(0xffffffffu, bi, o);
                if (ov > bv || (ov == bv && oi < bi)) { bv = ov; bi = oi; }
            }
            if (lane == 0) dout[1 + (size_t)r * 10 + it] = (float)bi;
#pragma unroll
            for (int p = 0; p < 3; p++)
                if (ci[p] == bi) { cv[p] = -INFINITY; ci[p] = 1 << 30; }
        }
    }
}

// ---------------- deterministic loss reduction (double) ----------------
__global__ void __launch_bounds__(256) loss_kernel(float* __restrict__ dout) {
    __shared__ double s[256];
    int tid = threadIdx.x;
    double a = 0.0;
    for (int i = 0; i < 32; i++) a += (double)g_rowloss[tid * 32 + i];
    s[tid] = a;
    __syncthreads();
    for (int o = 128; o > 0; o >>= 1) {
        if (tid < o) s[tid] += s[tid + o];
        __syncthreads();
    }
    if (tid == 0) dout[0] = (float)(s[0] / 8192.0);
}

extern "C" void kernel_launch(void* const* d_in, const int* in_sizes, int n_in,
                              void* d_out, int out_size) {
    const int*   pc        = (const int*)d_in[0];
    const int*   delta     = (const int*)d_in[1];
    const int*   clusters  = (const int*)d_in[2];
    const int*   target    = (const int*)d_in[3];
    const float* h0        = (const float*)d_in[4];
    const float* c0        = (const float*)d_in[5];
    const float* pc_emb    = (const float*)d_in[6];
    const float* delta_emb = (const float*)d_in[7];
    const float* w_ih0     = (const float*)d_in[8];
    const float* w_hh0     = (const float*)d_in[9];
    const float* b_ih0     = (const float*)d_in[10];
    const float* b_hh0     = (const float*)d_in[11];
    const float* w_ih1     = (const float*)d_in[12];
    const float* w_hh1     = (const float*)d_in[13];
    const float* b_ih1     = (const float*)d_in[14];
    const float* b_hh1     = (const float*)d_in[15];
    const float* Wc        = (const float*)d_in[16];
    const float* bc        = (const float*)d_in[17];
    float* out = (float*)d_out;

    static int smem_set = 0;
    int lstm_smem = 24960 * 4;
    if (!smem_set) {
        cudaFuncSetAttribute(lstm_kernel, cudaFuncAttributeMaxDynamicSharedMemorySize, lstm_smem);
        smem_set = 1;
    }

    float* g_Y0p = nullptr; float* g_Y1p = nullptr;
    cudaGetSymbolAddress((void**)&g_Y0p, g_Y0);
    cudaGetSymbolAddress((void**)&g_Y1p, g_Y1);

    noop_kernel<<<1, 32>>>();   // keeps ncu -s 5 capture on gemm_ih #2
    init_kernel<<<128, 256>>>(h0);
    embed_kernel<<<TB_, 128>>>(pc, delta, pc_emb, delta_emb);
    gemm_ih_kernel<<<dim3(16, 64), 256>>>(0, w_ih0);
    lstm_kernel<<<128, 256, lstm_smem>>>(w_hh0, c0, 0, 0, g_Y0p, out, b_ih0, b_hh0);
    gemm_ih_kernel<<<dim3(16, 64), 256>>>(1, w_ih1);
    lstm_kernel<<<128, 256, lstm_smem>>>(w_hh1, c0 + (size_t)B_ * H_, 1, 1, g_Y1p, out, b_ih1, b_hh1);
    logits_kernel<<<dim3(16, 256), 256>>>(clusters, Wc, bc);
    softmax_topk_kernel<<<TB_, 256>>>(target, out);
    loss_kernel<<<1, 256>>>(out);
}